// round 4
// baseline (speedup 1.0000x reference)
#include <cuda_runtime.h>
#include <cuda_bf16.h>
#include <stdint.h>

// ============================================================================
// Problem constants
// ============================================================================
#define NT      8192            // n_test == n_train
#define NF      64              // features
#define KD      512             // 64 feat * (4 levels hi + 4 levels lo)
#define TILE    128
#define NTI     (NT / TILE)     // 64
#define KCHUNK  64              // K per smem stage
#define CHUNKS  (KD / KCHUNK)   // 8
#define STAGES  3
#define STAGE_BYTES (TILE * KCHUNK * 2)       // 16 KB per operand per stage
#define SMEM_DYN (STAGES * 2 * STAGE_BYTES)   // 96 KB

// ============================================================================
// Device scratch (static __device__ globals: allocation-free)
// ============================================================================
__device__ __align__(128) __nv_bfloat16 g_Apk[(size_t)NT * KD]; // 8 MB
__device__ __align__(128) __nv_bfloat16 g_Bpk[(size_t)NT * KD]; // 8 MB
__device__ unsigned short g_whi[NF];
__device__ unsigned short g_wlo[NF];
__device__ float          g_base;
__device__ unsigned       g_rowmax[NT];

// ============================================================================
// PTX helpers (baseline sm_80-era instructions only — valid on plain sm_100)
// ============================================================================
__device__ __forceinline__ uint32_t smem_u32(const void* p) {
    uint32_t a;
    asm("{ .reg .u64 t; cvta.to.shared.u64 t, %1; cvt.u32.u64 %0, t; }"
        : "=r"(a) : "l"(p));
    return a;
}

__device__ __forceinline__ void cp16(uint32_t dst, const void* src) {
    asm volatile("cp.async.cg.shared.global [%0], [%1], 16;"
                 :: "r"(dst), "l"(src) : "memory");
}
__device__ __forceinline__ void cp_commit() {
    asm volatile("cp.async.commit_group;" ::: "memory");
}
template <int N>
__device__ __forceinline__ void cp_wait() {
    asm volatile("cp.async.wait_group %0;" :: "n"(N) : "memory");
}

__device__ __forceinline__ void ldm4(uint32_t& r0, uint32_t& r1, uint32_t& r2,
                                     uint32_t& r3, uint32_t addr) {
    asm volatile("ldmatrix.sync.aligned.m8n8.x4.shared.b16 {%0,%1,%2,%3}, [%4];"
                 : "=r"(r0), "=r"(r1), "=r"(r2), "=r"(r3) : "r"(addr));
}

__device__ __forceinline__ void mma16816(float& d0, float& d1, float& d2, float& d3,
                                         uint32_t a0, uint32_t a1, uint32_t a2, uint32_t a3,
                                         uint32_t b0, uint32_t b1) {
    asm volatile(
        "mma.sync.aligned.m16n8k16.row.col.f32.bf16.bf16.f32 "
        "{%0,%1,%2,%3}, {%4,%5,%6,%7}, {%8,%9}, {%0,%1,%2,%3};"
        : "+f"(d0), "+f"(d1), "+f"(d2), "+f"(d3)
        : "r"(a0), "r"(a1), "r"(a2), "r"(a3), "r"(b0), "r"(b1));
}

// Order-preserving float <-> unsigned encoding for atomicMax
__device__ __forceinline__ unsigned encf(float f) {
    unsigned u = __float_as_uint(f);
    return (u & 0x80000000u) ? ~u : (u | 0x80000000u);
}
__device__ __forceinline__ float decf(unsigned u) {
    return __uint_as_float((u & 0x80000000u) ? (u & 0x7FFFFFFFu) : ~u);
}

// ============================================================================
// Kernel 1: weights (bf16 hi/lo split) + base scalar
// ============================================================================
__global__ void k_prep(const float* __restrict__ bw) {
    __shared__ float sb[NF];
    int f = threadIdx.x;
    float h  = bw[f];
    float lf = logf(h / 3.0f);                 // log(h/(L-1))
    float w  = logf(1.0f - h) - lf;            // log_true - log_false
    __nv_bfloat16 hi = __float2bfloat16(w);
    float hif = __bfloat162float(hi);
    __nv_bfloat16 lo = __float2bfloat16(w - hif);
    g_whi[f] = __bfloat16_as_ushort(hi);
    g_wlo[f] = __bfloat16_as_ushort(lo);
    sb[f] = lf - logf(h);
    __syncthreads();
    if (f == 0) {
        float s = 0.0f;
        for (int k = 0; k < NF; k++) s += sb[k];
        g_base = s;
    }
}

// ============================================================================
// Kernel 2: reset row-max accumulator (every replay; deterministic)
// ============================================================================
__global__ void k_zero() {
    int i = blockIdx.x * blockDim.x + threadIdx.x;
    if (i < NT) g_rowmax[i] = 0u;   // below encoding of any finite float
}

// ============================================================================
// Kernel 3: one-hot bf16 operands, plain row-major [NT, 512]
//   K index = f*8 + slot; slots 0-3: hi plane levels 0-3; 4-7: lo plane.
// ============================================================================
__global__ void k_pack(const float* __restrict__ test, const float* __restrict__ train) {
    int idx = blockIdx.x * blockDim.x + threadIdx.x;  // row*64 + f
    int row = idx >> 6;
    int f   = idx & 63;
    size_t eoff = (size_t)row * KD + (size_t)f * 8;   // element offset (16B aligned)

    int t = (int)test[idx];
    uint32_t wh = (uint32_t)g_whi[f];
    uint32_t wl = (uint32_t)g_wlo[f];
    uint32_t a0 = (t == 0 ? wh : 0u) | ((t == 1 ? wh : 0u) << 16);
    uint32_t a1 = (t == 2 ? wh : 0u) | ((t == 3 ? wh : 0u) << 16);
    uint32_t a2 = (t == 0 ? wl : 0u) | ((t == 1 ? wl : 0u) << 16);
    uint32_t a3 = (t == 2 ? wl : 0u) | ((t == 3 ? wl : 0u) << 16);
    *reinterpret_cast<uint4*>(&g_Apk[eoff]) = make_uint4(a0, a1, a2, a3);

    int s = (int)train[idx];
    const uint32_t one = 0x3F80u;              // bf16 1.0
    uint32_t b0 = (s == 0 ? one : 0u) | ((s == 1 ? one : 0u) << 16);
    uint32_t b1 = (s == 2 ? one : 0u) | ((s == 3 ? one : 0u) << 16);
    *reinterpret_cast<uint4*>(&g_Bpk[eoff]) = make_uint4(b0, b1, b0, b1);
}

// ============================================================================
// Kernel 4: bf16 mma.sync GEMM 128x128xK512 + base + row max + store log_dist
// ============================================================================
__global__ void __launch_bounds__(256, 2) k_gemm(float* __restrict__ out) {
    extern __shared__ unsigned char smem_raw[];
    const uint32_t sA = smem_u32(smem_raw);
    const uint32_t sB = sA + STAGES * STAGE_BYTES;

    const int tid  = threadIdx.x;
    const int lane = tid & 31;
    const int wid  = tid >> 5;
    const int ti = blockIdx.x & (NTI - 1);   // M varies fastest: 64 consecutive CTAs share B panel
    const int tj = blockIdx.x >> 6;

    const unsigned char* Ag = (const unsigned char*)g_Apk + (size_t)ti * TILE * (KD * 2);
    const unsigned char* Bg = (const unsigned char*)g_Bpk + (size_t)tj * TILE * (KD * 2);

    // ---- cp.async copy mapping: 1024 x 16B per operand per stage, 256 threads x 4
    const int crow = tid >> 3;          // 0..31 (+32*i)
    const int cg   = tid & 7;           // 16B group within 128B row

    auto load_stage = [&](int stage, int chunk) {
        const uint32_t dA = sA + stage * STAGE_BYTES;
        const uint32_t dB = sB + stage * STAGE_BYTES;
        #pragma unroll
        for (int i = 0; i < 4; i++) {
            int row = crow + 32 * i;
            uint32_t doff = row * 128 + ((cg ^ (row & 7)) << 4);
            size_t   goff = (size_t)row * (KD * 2) + chunk * (KCHUNK * 2) + cg * 16;
            cp16(dA + doff, Ag + goff);
            cp16(dB + doff, Bg + goff);
        }
    };

    // ---- fragment addressing (smem-local rows)
    const int wm = wid >> 2, wn = wid & 3;
    const int Mb = wm * 64, Nb = wn * 32;

    int rA[4], rAoff[4];
    #pragma unroll
    for (int mt = 0; mt < 4; mt++) {
        rA[mt] = Mb + mt * 16 + (lane & 15);
        rAoff[mt] = rA[mt] * 128;
    }
    const int khA = lane >> 4;                 // k-half for A ldmatrix

    int rB[2], rBoff[2];
    #pragma unroll
    for (int p = 0; p < 2; p++) {
        rB[p] = Nb + p * 16 + ((lane >> 4) << 3) + (lane & 7);
        rBoff[p] = rB[p] * 128;
    }
    const int khB = (lane >> 3) & 1;           // k-half for B ldmatrix

    float d[4][4][4];
    #pragma unroll
    for (int mt = 0; mt < 4; mt++)
        #pragma unroll
        for (int nt = 0; nt < 4; nt++)
            #pragma unroll
            for (int q = 0; q < 4; q++) d[mt][nt][q] = 0.0f;

    // ---- pipeline prologue
    #pragma unroll
    for (int s = 0; s < STAGES - 1; s++) { load_stage(s, s); cp_commit(); }

    // ---- mainloop
    #pragma unroll 1
    for (int c = 0; c < CHUNKS; c++) {
        int pf = c + STAGES - 1;
        if (pf < CHUNKS) load_stage(pf % STAGES, pf);
        cp_commit();
        cp_wait<STAGES - 1>();
        __syncthreads();

        const uint32_t stA = sA + (c % STAGES) * STAGE_BYTES;
        const uint32_t stB = sB + (c % STAGES) * STAGE_BYTES;

        #pragma unroll
        for (int ks = 0; ks < 4; ks++) {
            uint32_t a[4][4];
            #pragma unroll
            for (int mt = 0; mt < 4; mt++) {
                uint32_t addr = stA + rAoff[mt] + (((ks * 2 + khA) ^ (rA[mt] & 7)) << 4);
                ldm4(a[mt][0], a[mt][1], a[mt][2], a[mt][3], addr);
            }
            uint32_t b[4][2];
            #pragma unroll
            for (int p = 0; p < 2; p++) {
                uint32_t addr = stB + rBoff[p] + (((ks * 2 + khB) ^ (rB[p] & 7)) << 4);
                ldm4(b[2*p][0], b[2*p][1], b[2*p+1][0], b[2*p+1][1], addr);
            }
            #pragma unroll
            for (int mt = 0; mt < 4; mt++)
                #pragma unroll
                for (int nt = 0; nt < 4; nt++)
                    mma16816(d[mt][nt][0], d[mt][nt][1], d[mt][nt][2], d[mt][nt][3],
                             a[mt][0], a[mt][1], a[mt][2], a[mt][3],
                             b[nt][0], b[nt][1]);
        }
        __syncthreads();
    }

    // ---- epilogue: add base, row max (quad shfl + atomicMax), float2 stores
    const float basev = g_base;
    const int orow0 = ti * TILE + Mb;
    const int ocol0 = tj * TILE + Nb + (lane & 3) * 2;

    #pragma unroll
    for (int mt = 0; mt < 4; mt++) {
        #pragma unroll
        for (int h = 0; h < 2; h++) {
            int r = orow0 + mt * 16 + (lane >> 2) + h * 8;
            float* orow = out + (size_t)r * NT + ocol0;
            float rmax = -3.4e38f;
            #pragma unroll
            for (int nt = 0; nt < 4; nt++) {
                float x = d[mt][nt][2 * h + 0] + basev;
                float y = d[mt][nt][2 * h + 1] + basev;
                rmax = fmaxf(rmax, fmaxf(x, y));
                *reinterpret_cast<float2*>(orow + nt * 8) = make_float2(x, y);
            }
            rmax = fmaxf(rmax, __shfl_xor_sync(0xffffffffu, rmax, 1));
            rmax = fmaxf(rmax, __shfl_xor_sync(0xffffffffu, rmax, 2));
            if ((lane & 3) == 0) atomicMax(&g_rowmax[r], encf(rmax));
        }
    }
}

// ============================================================================
// Kernel 5: out[i,j] = m_i * exp(log_dist[i,j] - m_i)   (in place, float4)
// ============================================================================
__global__ void k_final(float* __restrict__ out) {
    size_t idx = (size_t)blockIdx.x * blockDim.x + threadIdx.x;  // float4 index
    int i = (int)(idx >> 11);                                    // 2048 float4 per row
    float m = decf(g_rowmax[i]);
    float4 v = reinterpret_cast<float4*>(out)[idx];
    v.x = m * __expf(v.x - m);
    v.y = m * __expf(v.y - m);
    v.z = m * __expf(v.z - m);
    v.w = m * __expf(v.w - m);
    reinterpret_cast<float4*>(out)[idx] = v;
}

// ============================================================================
// Launch
// ============================================================================
extern "C" void kernel_launch(void* const* d_in, const int* in_sizes, int n_in,
                              void* d_out, int out_size) {
    (void)in_sizes; (void)n_in; (void)out_size;
    const float* bw    = (const float*)d_in[0];
    const float* test  = (const float*)d_in[1];
    const float* train = (const float*)d_in[2];
    float* out = (float*)d_out;

    cudaFuncSetAttribute(k_gemm, cudaFuncAttributeMaxDynamicSharedMemorySize, SMEM_DYN);

    k_prep<<<1, NF>>>(bw);
    k_zero<<<32, 256>>>();
    k_pack<<<(NT * NF) / 256, 256>>>(test, train);
    k_gemm<<<NTI * NTI, 256, SMEM_DYN>>>(out);
    k_final<<<(NT / 4) * (NT / 256), 256>>>(out);
}

// round 5
// speedup vs baseline: 1.4302x; 1.4302x over previous
#include <cuda_runtime.h>
#include <stdint.h>

// ============================================================================
// Problem constants
// ============================================================================
#define NT      8192            // n_test == n_train
#define NF      64              // features
#define KD      512             // 64 feat * (4 levels hi-digit + 4 levels lo-digit), u8
#define TILE    128
#define NTI     (NT / TILE)     // 64
#define KCHUNK  128             // K elements (bytes) per smem stage
#define CHUNKS  (KD / KCHUNK)   // 4
#define STAGES  3
#define STAGE_BYTES (TILE * KCHUNK)           // 16 KB per operand per stage
#define SMEM_DYN (STAGES * 2 * STAGE_BYTES)   // 96 KB

#define QSCALE  8070.0f         // w*S <= 32628 -> d1 = n>>7 <= 254 (u8), d0 = n&127
#define INV_QS  (1.0f / 8070.0f)

// ============================================================================
// Device scratch (static __device__ globals: allocation-free)
// ============================================================================
__device__ __align__(128) unsigned char g_Apk[(size_t)NT * KD]; // 4 MB
__device__ __align__(128) unsigned char g_Bpk[(size_t)NT * KD]; // 4 MB
__device__ unsigned char g_d1[NF];
__device__ unsigned char g_d0[NF];
__device__ float         g_base;
__device__ unsigned      g_rowmax[NT];

// ============================================================================
// PTX helpers (baseline sm_80-era instructions only — valid on plain sm_100)
// ============================================================================
__device__ __forceinline__ uint32_t smem_u32(const void* p) {
    uint32_t a;
    asm("{ .reg .u64 t; cvta.to.shared.u64 t, %1; cvt.u32.u64 %0, t; }"
        : "=r"(a) : "l"(p));
    return a;
}

__device__ __forceinline__ void cp16(uint32_t dst, const void* src) {
    asm volatile("cp.async.cg.shared.global [%0], [%1], 16;"
                 :: "r"(dst), "l"(src) : "memory");
}
__device__ __forceinline__ void cp_commit() {
    asm volatile("cp.async.commit_group;" ::: "memory");
}
template <int N>
__device__ __forceinline__ void cp_wait() {
    asm volatile("cp.async.wait_group %0;" :: "n"(N) : "memory");
}

__device__ __forceinline__ void ldm4(uint32_t& r0, uint32_t& r1, uint32_t& r2,
                                     uint32_t& r3, uint32_t addr) {
    asm volatile("ldmatrix.sync.aligned.m8n8.x4.shared.b16 {%0,%1,%2,%3}, [%4];"
                 : "=r"(r0), "=r"(r1), "=r"(r2), "=r"(r3) : "r"(addr));
}

// u8 x u8 -> s32, m16n8k32
__device__ __forceinline__ void imma16832(int& d0, int& d1, int& d2, int& d3,
                                          uint32_t a0, uint32_t a1, uint32_t a2, uint32_t a3,
                                          uint32_t b0, uint32_t b1) {
    asm volatile(
        "mma.sync.aligned.m16n8k32.row.col.s32.u8.u8.s32 "
        "{%0,%1,%2,%3}, {%4,%5,%6,%7}, {%8,%9}, {%0,%1,%2,%3};"
        : "+r"(d0), "+r"(d1), "+r"(d2), "+r"(d3)
        : "r"(a0), "r"(a1), "r"(a2), "r"(a3), "r"(b0), "r"(b1));
}

// Order-preserving float <-> unsigned encoding for atomicMax
__device__ __forceinline__ unsigned encf(float f) {
    unsigned u = __float_as_uint(f);
    return (u & 0x80000000u) ? ~u : (u | 0x80000000u);
}
__device__ __forceinline__ float decf(unsigned u) {
    return __uint_as_float((u & 0x80000000u) ? (u & 0x7FFFFFFFu) : ~u);
}

// ============================================================================
// Kernel 1: weights -> base-128 u8 digits + base scalar
// ============================================================================
__global__ void k_prep(const float* __restrict__ bw) {
    __shared__ float sb[NF];
    int f = threadIdx.x;
    float h  = bw[f];
    float lf = logf(h / 3.0f);                 // log(h/(L-1))
    float w  = logf(1.0f - h) - lf;            // log_true - log_false (> 0)
    int n = (int)rintf(w * QSCALE);
    if (n > 32639) n = 32639;                  // 254*128+127 safety clamp
    if (n < 0) n = 0;
    g_d1[f] = (unsigned char)(n >> 7);
    g_d0[f] = (unsigned char)(n & 127);
    sb[f] = lf - logf(h);
    __syncthreads();
    if (f == 0) {
        float s = 0.0f;
        for (int k = 0; k < NF; k++) s += sb[k];
        g_base = s;
    }
}

// ============================================================================
// Kernel 2: reset row-max accumulator (every replay; deterministic)
// ============================================================================
__global__ void k_zero() {
    int i = blockIdx.x * blockDim.x + threadIdx.x;
    if (i < NT) g_rowmax[i] = 0u;   // below encoding of any finite float
}

// ============================================================================
// Kernel 3: one-hot u8 operands, row-major [NT, 512] bytes
//   K byte = f*8 + slot; slots 0-3: hi-digit plane; 4-7: lo-digit plane.
//   A carries digits d1/d0; B carries 128/1 one-hot (digit weight folded in B).
// ============================================================================
__global__ void k_pack(const float* __restrict__ test, const float* __restrict__ train) {
    int idx = blockIdx.x * blockDim.x + threadIdx.x;  // row*64 + f
    int row = idx >> 6;
    int f   = idx & 63;
    size_t eoff = (size_t)row * KD + (size_t)f * 8;   // byte offset (8B aligned)

    int t = (int)test[idx];                            // exactly one level in 0..3
    uint32_t d1 = g_d1[f], d0 = g_d0[f];
    uint2 av = make_uint2(d1 << (t * 8), d0 << (t * 8));
    *reinterpret_cast<uint2*>(g_Apk + eoff) = av;

    int s = (int)train[idx];
    uint2 bv = make_uint2(128u << (s * 8), 1u << (s * 8));
    *reinterpret_cast<uint2*>(g_Bpk + eoff) = bv;
}

// ============================================================================
// Kernel 4: u8 IMMA GEMM 128x128xK512 + base + row max + store log_dist
// ============================================================================
__global__ void __launch_bounds__(256, 2) k_gemm(float* __restrict__ out) {
    extern __shared__ unsigned char smem_raw[];
    const uint32_t sA = smem_u32(smem_raw);
    const uint32_t sB = sA + STAGES * STAGE_BYTES;

    const int tid  = threadIdx.x;
    const int lane = tid & 31;
    const int wid  = tid >> 5;
    const int ti = blockIdx.x & (NTI - 1);   // M varies fastest: 64 consecutive CTAs share B panel
    const int tj = blockIdx.x >> 6;

    const unsigned char* Ag = g_Apk + (size_t)ti * TILE * KD;
    const unsigned char* Bg = g_Bpk + (size_t)tj * TILE * KD;

    // ---- cp.async copy mapping: 1024 x 16B per operand per stage, 256 threads x 4
    const int crow = tid >> 3;          // 0..31 (+32*i)
    const int cg   = tid & 7;           // 16B group within 128B row

    auto load_stage = [&](int stage, int chunk) {
        const uint32_t dA = sA + stage * STAGE_BYTES;
        const uint32_t dB = sB + stage * STAGE_BYTES;
        #pragma unroll
        for (int i = 0; i < 4; i++) {
            int row = crow + 32 * i;
            uint32_t doff = row * 128 + ((cg ^ (row & 7)) << 4);
            size_t   goff = (size_t)row * KD + chunk * KCHUNK + cg * 16;
            cp16(dA + doff, Ag + goff);
            cp16(dB + doff, Bg + goff);
        }
    };

    // ---- fragment addressing (smem-local rows; 16B k-groups, same geometry as bf16)
    const int wm = wid >> 2, wn = wid & 3;
    const int Mb = wm * 64, Nb = wn * 32;

    int rA[4], rAoff[4];
    #pragma unroll
    for (int mt = 0; mt < 4; mt++) {
        rA[mt] = Mb + mt * 16 + (lane & 15);
        rAoff[mt] = rA[mt] * 128;
    }
    const int khA = lane >> 4;                 // k-half (16B) for A ldmatrix

    int rB[2], rBoff[2];
    #pragma unroll
    for (int p = 0; p < 2; p++) {
        rB[p] = Nb + p * 16 + ((lane >> 4) << 3) + (lane & 7);
        rBoff[p] = rB[p] * 128;
    }
    const int khB = (lane >> 3) & 1;           // k-half (16B) for B ldmatrix

    int d[4][4][4];
    #pragma unroll
    for (int mt = 0; mt < 4; mt++)
        #pragma unroll
        for (int nt = 0; nt < 4; nt++)
            #pragma unroll
            for (int q = 0; q < 4; q++) d[mt][nt][q] = 0;

    // ---- pipeline prologue
    #pragma unroll
    for (int s = 0; s < STAGES - 1; s++) { load_stage(s, s); cp_commit(); }

    // ---- mainloop: 4 chunks x 4 k32-steps
    #pragma unroll 1
    for (int c = 0; c < CHUNKS; c++) {
        int pf = c + STAGES - 1;
        if (pf < CHUNKS) load_stage(pf % STAGES, pf);
        cp_commit();
        cp_wait<STAGES - 1>();
        __syncthreads();

        const uint32_t stA = sA + (c % STAGES) * STAGE_BYTES;
        const uint32_t stB = sB + (c % STAGES) * STAGE_BYTES;

        #pragma unroll
        for (int ks = 0; ks < 4; ks++) {
            uint32_t a[4][4];
            #pragma unroll
            for (int mt = 0; mt < 4; mt++) {
                uint32_t addr = stA + rAoff[mt] + (((ks * 2 + khA) ^ (rA[mt] & 7)) << 4);
                ldm4(a[mt][0], a[mt][1], a[mt][2], a[mt][3], addr);
            }
            uint32_t b[4][2];
            #pragma unroll
            for (int p = 0; p < 2; p++) {
                uint32_t addr = stB + rBoff[p] + (((ks * 2 + khB) ^ (rB[p] & 7)) << 4);
                ldm4(b[2*p][0], b[2*p][1], b[2*p+1][0], b[2*p+1][1], addr);
            }
            #pragma unroll
            for (int mt = 0; mt < 4; mt++)
                #pragma unroll
                for (int nt = 0; nt < 4; nt++)
                    imma16832(d[mt][nt][0], d[mt][nt][1], d[mt][nt][2], d[mt][nt][3],
                              a[mt][0], a[mt][1], a[mt][2], a[mt][3],
                              b[nt][0], b[nt][1]);
        }
        __syncthreads();
    }

    // ---- epilogue: dequant + base, row max (quad shfl + atomicMax), float2 stores
    const float basev = g_base;
    const int orow0 = ti * TILE + Mb;
    const int ocol0 = tj * TILE + Nb + (lane & 3) * 2;

    #pragma unroll
    for (int mt = 0; mt < 4; mt++) {
        #pragma unroll
        for (int h = 0; h < 2; h++) {
            int r = orow0 + mt * 16 + (lane >> 2) + h * 8;
            float* orow = out + (size_t)r * NT + ocol0;
            float rmax = -3.4e38f;
            #pragma unroll
            for (int nt = 0; nt < 4; nt++) {
                float x = fmaf((float)d[mt][nt][2 * h + 0], INV_QS, basev);
                float y = fmaf((float)d[mt][nt][2 * h + 1], INV_QS, basev);
                rmax = fmaxf(rmax, fmaxf(x, y));
                *reinterpret_cast<float2*>(orow + nt * 8) = make_float2(x, y);
            }
            rmax = fmaxf(rmax, __shfl_xor_sync(0xffffffffu, rmax, 1));
            rmax = fmaxf(rmax, __shfl_xor_sync(0xffffffffu, rmax, 2));
            if ((lane & 3) == 0) atomicMax(&g_rowmax[r], encf(rmax));
        }
    }
}

// ============================================================================
// Kernel 5: out[i,j] = m_i * exp(log_dist[i,j] - m_i)   (in place, float4)
// ============================================================================
__global__ void k_final(float* __restrict__ out) {
    size_t idx = (size_t)blockIdx.x * blockDim.x + threadIdx.x;  // float4 index
    int i = (int)(idx >> 11);                                    // 2048 float4 per row
    float m = decf(g_rowmax[i]);
    float4 v = reinterpret_cast<float4*>(out)[idx];
    v.x = m * __expf(v.x - m);
    v.y = m * __expf(v.y - m);
    v.z = m * __expf(v.z - m);
    v.w = m * __expf(v.w - m);
    reinterpret_cast<float4*>(out)[idx] = v;
}

// ============================================================================
// Launch
// ============================================================================
extern "C" void kernel_launch(void* const* d_in, const int* in_sizes, int n_in,
                              void* d_out, int out_size) {
    (void)in_sizes; (void)n_in; (void)out_size;
    const float* bw    = (const float*)d_in[0];
    const float* test  = (const float*)d_in[1];
    const float* train = (const float*)d_in[2];
    float* out = (float*)d_out;

    cudaFuncSetAttribute(k_gemm, cudaFuncAttributeMaxDynamicSharedMemorySize, SMEM_DYN);

    k_prep<<<1, NF>>>(bw);
    k_zero<<<32, 256>>>();
    k_pack<<<(NT * NF) / 256, 256>>>(test, train);
    k_gemm<<<NTI * NTI, 256, SMEM_DYN>>>(out);
    k_final<<<(NT / 4) * (NT / 256), 256>>>(out);
}